// round 17
// baseline (speedup 1.0000x reference)
#include <cuda_runtime.h>
#include <cuda_bf16.h>

// x (64, 96, 8, 8) fp32 -> out (64, 96, 96, 8, 8, 2) fp32
// out[b,i,j,c1,c2,0] = x[b,i,c1,c2]; out[b,i,j,c1,c2,1] = x[b,j,c1,c2]
//
// Proven R9 body (best-known: 1 xi load reused + 4 independent xj loads ->
// 4 independent 512B-coalesced STG.128 per thread; 128-thread blocks).
// Single change: 40KB of (unused) dynamic shared memory per block caps
// occupancy at ~5 CTAs/SM, cutting concurrent DRAM write streams ~3x to
// improve HBM write locality (row activation / turnaround efficiency).
// Stores are fire-and-forget: 20 warps/SM still saturate LSU store issue.

#define GS  96
#define BLK 64            // 8*8 floats per group block
#define F4  32            // float4 per (b,i,j) pair
#define JT  6             // j-tiles per (b,i): 6 * 16 = 96

__global__ __launch_bounds__(128)
void gcom_kernel(const float* __restrict__ x, float4* __restrict__ out)
{
    unsigned blk = blockIdx.x;             // (b*96 + i)*6 + jt
    unsigned jt  = blk % JT;
    unsigned bi  = blk / JT;               // b*96 + i
    unsigned b   = bi / GS;
    unsigned i   = bi - b * GS;

    unsigned lane = threadIdx.x & 31u;     // k2: float2 index within 64-float block
    unsigned w    = threadIdx.x >> 5;      // warp 0..3
    unsigned j0   = jt * 16 + w * 4;       // first of 4 j's for this warp

    const float2* xrow = (const float2*)(x + (size_t)b * GS * BLK);

    // All loads issued up front (independent; xi reused for 4 stores).
    float2 a  = __ldg(xrow + i * F4 + lane);
    const float2* xj = xrow + j0 * F4 + lane;
    float2 c0 = __ldg(xj);
    float2 c1 = __ldg(xj + F4);
    float2 c2 = __ldg(xj + 2 * F4);
    float2 c3 = __ldg(xj + 3 * F4);

    float4* o = out + ((size_t)bi * GS + j0) * F4 + lane;
    o[0]      = make_float4(a.x, c0.x, a.y, c0.y);
    o[F4]     = make_float4(a.x, c1.x, a.y, c1.y);
    o[2 * F4] = make_float4(a.x, c2.x, a.y, c2.y);
    o[3 * F4] = make_float4(a.x, c3.x, a.y, c3.y);
}

extern "C" void kernel_launch(void* const* d_in, const int* in_sizes, int n_in,
                              void* d_out, int out_size)
{
    const float* x = (const float*)d_in[0];
    float4* out = (float4*)d_out;

    // 64 * 96 * 6 = 36864 blocks; 40KB dynamic smem (unused) caps occupancy
    // at ~5 CTAs/SM to reduce concurrent DRAM write streams.
    gcom_kernel<<<64 * GS * JT, 128, 40960>>>(x, out);
}